// round 3
// baseline (speedup 1.0000x reference)
#include <cuda_runtime.h>

#define BATCH   4
#define NPTS    8192
#define THREADS 256
#define QPT     4
#define QTILE   (THREADS * QPT)     // 1024 queries per block
#define JSPLIT  8
#define JCHUNK  (NPTS / JSPLIT)     // 1024 ref points per block
#define JTILE   512                 // smem tile of ref points

typedef unsigned long long ull;

// Persistent scratch: packed (dist_bits<<32)|idx per (dir, b*N + q). 512 KB.
__device__ ull g_best[2][BATCH * NPTS];

// ---- packed fp32x2 helpers (Blackwell sm_103a). Explicit .rn, no contraction. ----
static __device__ __forceinline__ ull pk2(float lo, float hi) {
    ull r; asm("mov.b64 %0, {%1, %2};" : "=l"(r) : "f"(lo), "f"(hi)); return r;
}
static __device__ __forceinline__ void up2(ull v, float& lo, float& hi) {
    asm("mov.b64 {%0, %1}, %2;" : "=f"(lo), "=f"(hi) : "l"(v));
}
static __device__ __forceinline__ ull add2(ull a, ull b) {
    ull r; asm("add.rn.f32x2 %0, %1, %2;" : "=l"(r) : "l"(a), "l"(b)); return r;
}
static __device__ __forceinline__ ull mul2(ull a, ull b) {
    ull r; asm("mul.rn.f32x2 %0, %1, %2;" : "=l"(r) : "l"(a), "l"(b)); return r;
}

__global__ void init_best_kernel() {
    int i = blockIdx.x * blockDim.x + threadIdx.x;
    if (i < 2 * BATCH * NPTS)
        (&g_best[0][0])[i] = 0xFFFFFFFFFFFFFFFFull;
}

// One direction: for each query point in qpts, min squared distance over rpts.
// Grid: x = (NPTS/QTILE) * JSPLIT, y = BATCH. Each block scans JCHUNK ref pts
// for QTILE queries; partial results merged via 64-bit atomicMin.
__global__ void __launch_bounds__(THREADS)
chamfer_dir_kernel(const float* __restrict__ qpts,
                   const float* __restrict__ rpts,
                   int dir)
{
    __shared__ float4 tile[JTILE];

    const int b   = blockIdx.y;
    const int qt  = blockIdx.x / JSPLIT;
    const int jc  = blockIdx.x % JSPLIT;
    const int tid = threadIdx.x;

    const float* qb = qpts + (size_t)b * NPTS * 3;
    const float* rb = rpts + (size_t)b * NPTS * 3;

    // Load 4 queries per thread (strided for coalescing), pack as f32x2 pairs.
    const int q0 = qt * QTILE + tid;
    float qx[QPT], qy[QPT], qz[QPT];
#pragma unroll
    for (int k = 0; k < QPT; k++) {
        int qi = q0 + k * THREADS;
        qx[k] = qb[qi * 3 + 0];
        qy[k] = qb[qi * 3 + 1];
        qz[k] = qb[qi * 3 + 2];
    }
    const ull qx01 = pk2(qx[0], qx[1]), qx23 = pk2(qx[2], qx[3]);
    const ull qy01 = pk2(qy[0], qy[1]), qy23 = pk2(qy[2], qy[3]);
    const ull qz01 = pk2(qz[0], qz[1]), qz23 = pk2(qz[2], qz[3]);

    float bd[QPT];
    int   bj[QPT];
#pragma unroll
    for (int k = 0; k < QPT; k++) { bd[k] = 3.4e38f; bj[k] = 0; }

    const int jbase_chunk = jc * JCHUNK;

    for (int jt = 0; jt < JCHUNK; jt += JTILE) {
        __syncthreads();
        // Stage JTILE ref points (negated so dx = qx + (-rx), rounding-exact).
        for (int l = tid; l < JTILE; l += THREADS) {
            int j = jbase_chunk + jt + l;
            tile[l] = make_float4(-rb[j * 3 + 0], -rb[j * 3 + 1], -rb[j * 3 + 2], 0.0f);
        }
        __syncthreads();

        const int jg0 = jbase_chunk + jt;
#pragma unroll 4
        for (int jj = 0; jj < JTILE; jj++) {
            float4 p = tile[jj];
            ull px = pk2(p.x, p.x);
            ull py = pk2(p.y, p.y);
            ull pz = pk2(p.z, p.z);

            ull dx01 = add2(qx01, px), dy01 = add2(qy01, py), dz01 = add2(qz01, pz);
            ull dx23 = add2(qx23, px), dy23 = add2(qy23, py), dz23 = add2(qz23, pz);

            // d = (dx*dx + dy*dy) + dz*dz  -- plain mul/add, matches reference order
            ull s01 = add2(add2(mul2(dx01, dx01), mul2(dy01, dy01)), mul2(dz01, dz01));
            ull s23 = add2(add2(mul2(dx23, dx23), mul2(dy23, dy23)), mul2(dz23, dz23));

            float d0, d1, d2, d3;
            up2(s01, d0, d1);
            up2(s23, d2, d3);

            const int jg = jg0 + jj;
            if (d0 < bd[0]) { bd[0] = d0; bj[0] = jg; }
            if (d1 < bd[1]) { bd[1] = d1; bj[1] = jg; }
            if (d2 < bd[2]) { bd[2] = d2; bj[2] = jg; }
            if (d3 < bd[3]) { bd[3] = d3; bj[3] = jg; }
        }
    }

    ull* dst = &g_best[dir][b * NPTS];
#pragma unroll
    for (int k = 0; k < QPT; k++) {
        int qi = q0 + k * THREADS;
        ull key = ((ull)__float_as_uint(bd[k]) << 32) | (unsigned)bj[k];
        atomicMin(dst + qi, key);
    }
}

// Unpack scratch into output: [dist1 | dist2 | idx1 | idx2], all float32.
__global__ void finalize_kernel(float* __restrict__ out) {
    int i = blockIdx.x * blockDim.x + threadIdx.x;
    if (i >= BATCH * NPTS) return;
    ull k1 = g_best[0][i];
    ull k2 = g_best[1][i];
    out[0 * BATCH * NPTS + i] = __uint_as_float((unsigned)(k1 >> 32));
    out[1 * BATCH * NPTS + i] = __uint_as_float((unsigned)(k2 >> 32));
    out[2 * BATCH * NPTS + i] = (float)(int)(k1 & 0xFFFFFFFFu);
    out[3 * BATCH * NPTS + i] = (float)(int)(k2 & 0xFFFFFFFFu);
}

extern "C" void kernel_launch(void* const* d_in, const int* in_sizes, int n_in,
                              void* d_out, int out_size) {
    const float* xyz1 = (const float*)d_in[0];
    const float* xyz2 = (const float*)d_in[1];
    float* out = (float*)d_out;

    init_best_kernel<<<(2 * BATCH * NPTS + 255) / 256, 256>>>();

    dim3 grid((NPTS / QTILE) * JSPLIT, BATCH);
    chamfer_dir_kernel<<<grid, THREADS>>>(xyz1, xyz2, 0);  // dist1/idx1
    chamfer_dir_kernel<<<grid, THREADS>>>(xyz2, xyz1, 1);  // dist2/idx2

    finalize_kernel<<<(BATCH * NPTS + 255) / 256, 256>>>(out);
}